// round 4
// baseline (speedup 1.0000x reference)
#include <cuda_runtime.h>
#include <cuda_bf16.h>
#include <cstdint>

// ======================= problem sizes =======================
constexpr int K_DIM = 4096;
constexpr int M_DIM = 4096;     // 2*2048 tokens
constexpr int N_DIM = 16384;

constexpr int BM = 128, BN = 128, BK = 64;
constexpr int MT = M_DIM / BM;   // 32
constexpr int NT = N_DIM / BN;   // 128
constexpr int KT = K_DIM / BK;   // 64
constexpr int STAGES = 4;

constexpr uint32_t A_TILE_B = BM * BK;                // 8192 bytes (int8)
constexpr uint32_t B_TILE_B = BN * BK;                // 8192 bytes (int8)
constexpr uint32_t STAGE_B  = A_TILE_B + B_TILE_B;    // 16384 bytes
constexpr uint32_t SMEM_STAGE0 = 1024;
constexpr uint32_t SMEM_SIZE = SMEM_STAGE0 + STAGES * STAGE_B;  // 66560

// SMEM offsets for barriers
constexpr uint32_t OFF_FULL  = 0;    // full[s]  at 0  + 16*s
constexpr uint32_t OFF_EMPTY = 8;    // empty[s] at 8  + 16*s

// int8 quantized scratch in IMMA fragment order
__device__ __align__(1024) unsigned char g_Aq[(size_t)M_DIM * K_DIM]; // 16 MB
__device__ __align__(1024) unsigned char g_Bq[(size_t)N_DIM * K_DIM]; // 64 MB

// ======================= helpers =======================
static __device__ __forceinline__ uint32_t smem_u32(const void* p) {
    uint32_t a;
    asm("{ .reg .u64 t; cvta.to.shared.u64 t, %1; cvt.u32.u64 %0, t; }"
        : "=r"(a) : "l"(p));
    return a;
}
static __device__ __forceinline__ void mbar_init(uint32_t mbar, uint32_t cnt) {
    asm volatile("mbarrier.init.shared.b64 [%0], %1;" :: "r"(mbar), "r"(cnt) : "memory");
}
static __device__ __forceinline__ void mbar_expect_tx(uint32_t mbar, uint32_t bytes) {
    asm volatile("mbarrier.arrive.expect_tx.shared.b64 _, [%0], %1;"
                 :: "r"(mbar), "r"(bytes) : "memory");
}
static __device__ __forceinline__ void mbar_arrive(uint32_t mbar) {
    asm volatile("mbarrier.arrive.shared.b64 _, [%0];" :: "r"(mbar) : "memory");
}
static __device__ __forceinline__ void mbar_wait(uint32_t mbar, uint32_t parity) {
    asm volatile(
        "{\n\t.reg .pred P;\n\t"
        "W%=:\n\t"
        "mbarrier.try_wait.parity.acquire.cta.shared::cta.b64 P, [%0], %1, 0x989680;\n\t"
        "@P bra.uni D%=;\n\t"
        "bra.uni W%=;\n\t"
        "D%=:\n\t}"
        :: "r"(mbar), "r"(parity) : "memory");
}
static __device__ __forceinline__ void bulk_g2s(uint32_t dst, const void* src,
                                                uint32_t bytes, uint32_t mbar) {
    asm volatile(
        "cp.async.bulk.shared::cluster.global.mbarrier::complete_tx::bytes "
        "[%0], [%1], %2, [%3];"
        :: "r"(dst), "l"(src), "r"(bytes), "r"(mbar) : "memory");
}
static __device__ __forceinline__ void lds128(uint32_t& r0, uint32_t& r1,
                                              uint32_t& r2, uint32_t& r3, uint32_t a) {
    asm volatile("ld.shared.v4.b32 {%0,%1,%2,%3}, [%4];"
                 : "=r"(r0), "=r"(r1), "=r"(r2), "=r"(r3) : "r"(a));
}
static __device__ __forceinline__ void lds64(uint32_t& r0, uint32_t& r1, uint32_t a) {
    asm volatile("ld.shared.v2.b32 {%0,%1}, [%2];" : "=r"(r0), "=r"(r1) : "r"(a));
}
static __device__ __forceinline__ void imma16832(int& c0, int& c1, int& c2, int& c3,
                                                 uint32_t a0, uint32_t a1, uint32_t a2,
                                                 uint32_t a3, uint32_t b0, uint32_t b1) {
    asm volatile(
        "mma.sync.aligned.m16n8k32.row.col.s32.s8.s8.s32 "
        "{%0,%1,%2,%3}, {%4,%5,%6,%7}, {%8,%9}, {%0,%1,%2,%3};"
        : "+r"(c0), "+r"(c1), "+r"(c2), "+r"(c3)
        : "r"(a0), "r"(a1), "r"(a2), "r"(a3), "r"(b0), "r"(b1));
}
static __device__ __forceinline__ uint32_t quant_pack4(float4 v, float c, float inv) {
    int q0 = __float2int_rn(fminf(fmaxf(v.x, -c), c) * inv);
    int q1 = __float2int_rn(fminf(fmaxf(v.y, -c), c) * inv);
    int q2 = __float2int_rn(fminf(fmaxf(v.z, -c), c) * inv);
    int q3 = __float2int_rn(fminf(fmaxf(v.w, -c), c) * inv);
    return (uint32_t)(q0 & 255) | ((uint32_t)(q1 & 255) << 8) |
           ((uint32_t)(q2 & 255) << 16) | ((uint32_t)(q3 & 255) << 24);
}

// ======================= quantize kernels =======================
// A fragment order: tile(mt,kt) 8192B = [kc(2)][ma(8)] atoms of 512B,
// atom = [lane(32)][a0,a1,a2,a3] where per IMMA m16n8k32:
//   a0=(row g,    k tt*4+0..3)  a1=(row g+8, same k)
//   a2=(row g,    k 16+tt*4)    a3=(row g+8, k 16+tt*4)
// One thread produces one lane's 16 bytes -> total threads = M*K/16 = 1,048,576
__global__ void __launch_bounds__(256) quant_a_kernel(const float* __restrict__ x,
                                                      const float* __restrict__ clip) {
    uint32_t t = blockIdx.x * 256u + threadIdx.x;
    uint32_t lane = t & 31u;
    uint32_t rest = t >> 5;
    uint32_t amkc = rest & 15u;           // kc*8 + ma
    uint32_t kt   = (rest >> 4) & 63u;
    uint32_t mt   = rest >> 10;
    uint32_t kc = amkc >> 3, ma = amkc & 7u;
    uint32_t g = lane >> 2, tt = lane & 3u;

    float c = fabsf(__ldg(clip));
    float inv = 127.0f / c;

    uint32_t row0 = mt * 128u + ma * 16u + g;
    uint32_t col0 = kt * 64u + kc * 32u + tt * 4u;
    const float* base = x + (size_t)row0 * K_DIM + col0;

    float4 f0 = *reinterpret_cast<const float4*>(base);
    float4 f1 = *reinterpret_cast<const float4*>(base + 8u * K_DIM);
    float4 f2 = *reinterpret_cast<const float4*>(base + 16);
    float4 f3 = *reinterpret_cast<const float4*>(base + 8u * K_DIM + 16);

    uint4 p;
    p.x = quant_pack4(f0, c, inv);
    p.y = quant_pack4(f1, c, inv);
    p.z = quant_pack4(f2, c, inv);
    p.w = quant_pack4(f3, c, inv);

    size_t off = ((size_t)(mt * 64u + kt) * 16u + amkc) * 512u + lane * 16u;
    *reinterpret_cast<uint4*>(g_Aq + off) = p;
}

// B fragment order: tile(nt,kt) 8192B = [kc(2)][na(16)] atoms of 256B,
// atom = [lane(32)][b0,b1] where  b0=(k tt*4+0..3, col g)  b1=(k 16+tt*4, col g)
// One thread produces one lane's 8 bytes -> total threads = N*K/8 = 8,388,608
__global__ void __launch_bounds__(256) quant_b_kernel(const float* __restrict__ w,
                                                      const float* __restrict__ clip) {
    uint32_t t = blockIdx.x * 256u + threadIdx.x;
    uint32_t lane = t & 31u;
    uint32_t rest = t >> 5;
    uint32_t ankc = rest & 31u;           // kc*16 + na
    uint32_t kt   = (rest >> 5) & 63u;
    uint32_t nt   = rest >> 11;
    uint32_t kc = ankc >> 4, na = ankc & 15u;
    uint32_t g = lane >> 2, tt = lane & 3u;

    float c = fabsf(__ldg(clip));
    float inv = 127.0f / c;

    uint32_t n  = nt * 128u + na * 8u + g;
    uint32_t k0 = kt * 64u + kc * 32u + tt * 4u;
    const float* base = w + (size_t)n * K_DIM + k0;

    float4 f0 = *reinterpret_cast<const float4*>(base);
    float4 f1 = *reinterpret_cast<const float4*>(base + 16);

    uint2 p;
    p.x = quant_pack4(f0, c, inv);
    p.y = quant_pack4(f1, c, inv);

    size_t off = ((size_t)(nt * 64u + kt) * 32u + ankc) * 256u + lane * 8u;
    *reinterpret_cast<uint2*>(g_Bq + off) = p;
}

// ======================= GEMM kernel =======================
// out[m][n] = relu( sc * sum_k qx[m][k]*qw[n][k] + bias[n] ),  sc = (cx/127)*(cw/127)
__global__ void __launch_bounds__(128, 2) gemm_kernel(const float* __restrict__ bias,
                                                      const float* __restrict__ clip_w,
                                                      const float* __restrict__ clip_x,
                                                      float* __restrict__ out) {
    extern __shared__ unsigned char smem[];
    const uint32_t sb = smem_u32(smem);
    const int tid = threadIdx.x;
    const uint32_t lane = tid & 31, wid = tid >> 5;
    const uint32_t wm = wid & 1, wn = wid >> 1;   // 2x2 warp grid, warp tile 64x64
    const uint32_t g = lane >> 2, tt = lane & 3;

    const uint32_t bid = blockIdx.x;
    const uint32_t mt = bid & 31u;    // m-fastest: 32 CTAs share one B column
    const uint32_t nt = bid >> 5;

    if (tid == 0) {
        for (int s = 0; s < STAGES; s++) {
            mbar_init(sb + OFF_FULL  + 16u * s, 1);
            mbar_init(sb + OFF_EMPTY + 16u * s, 128);
        }
    }
    __syncthreads();

    const unsigned char* aAg = g_Aq + (size_t)mt * KT * A_TILE_B;
    const unsigned char* bAg = g_Bq + (size_t)nt * KT * B_TILE_B;

    // prologue: fill all stages
    if (tid == 0) {
#pragma unroll
        for (int p = 0; p < STAGES; ++p) {
            uint32_t full = sb + OFF_FULL + 16u * p;
            uint32_t dst = sb + SMEM_STAGE0 + p * STAGE_B;
            mbar_expect_tx(full, STAGE_B);
            bulk_g2s(dst,            aAg + (size_t)p * A_TILE_B, A_TILE_B, full);
            bulk_g2s(dst + A_TILE_B, bAg + (size_t)p * B_TILE_B, B_TILE_B, full);
        }
    }

    int acc[4][8][4];
#pragma unroll
    for (int i = 0; i < 4; i++)
#pragma unroll
        for (int j = 0; j < 8; j++)
#pragma unroll
            for (int r = 0; r < 4; r++) acc[i][j][r] = 0;

    const uint32_t aLane = lane * 16u + wm * 4u * 512u;   // + kc*4096 + i*512
    const uint32_t bLane = lane * 8u + wn * 8u * 256u;    // + kc*4096 + j*256

    for (int kt = 0; kt < KT; ++kt) {
        const int s = kt & 3;
        const uint32_t ph = (kt >> 2) & 1u;
        const uint32_t stage = sb + SMEM_STAGE0 + s * STAGE_B;

        mbar_wait(sb + OFF_FULL + 16u * s, ph);

#pragma unroll
        for (int kc = 0; kc < 2; ++kc) {
            uint32_t a[4][4], b[8][2];
            const uint32_t aBase = stage + kc * 4096u + aLane;
            const uint32_t bBase = stage + A_TILE_B + kc * 4096u + bLane;
#pragma unroll
            for (int i = 0; i < 4; ++i)
                lds128(a[i][0], a[i][1], a[i][2], a[i][3], aBase + i * 512u);
#pragma unroll
            for (int j = 0; j < 8; ++j)
                lds64(b[j][0], b[j][1], bBase + j * 256u);
#pragma unroll
            for (int i = 0; i < 4; ++i)
#pragma unroll
                for (int j = 0; j < 8; ++j)
                    imma16832(acc[i][j][0], acc[i][j][1], acc[i][j][2], acc[i][j][3],
                              a[i][0], a[i][1], a[i][2], a[i][3], b[j][0], b[j][1]);
        }

        mbar_arrive(sb + OFF_EMPTY + 16u * s);

        if (tid == 0) {
            int nk = kt + STAGES;
            if (nk < KT) {
                mbar_wait(sb + OFF_EMPTY + 16u * s, ph);
                uint32_t full = sb + OFF_FULL + 16u * s;
                mbar_expect_tx(full, STAGE_B);
                bulk_g2s(stage,            aAg + (size_t)nk * A_TILE_B, A_TILE_B, full);
                bulk_g2s(stage + A_TILE_B, bAg + (size_t)nk * B_TILE_B, B_TILE_B, full);
            }
        }
    }

    // -------- epilogue --------
    const float sc = (fabsf(__ldg(clip_x)) / 127.0f) * (fabsf(__ldg(clip_w)) / 127.0f);

#pragma unroll
    for (int i = 0; i < 4; ++i) {
        const uint32_t r0 = mt * 128u + wm * 64u + i * 16u + g;
        float* orow0 = out + (size_t)r0 * N_DIM;
        float* orow1 = orow0 + (size_t)8 * N_DIM;
#pragma unroll
        for (int j = 0; j < 8; ++j) {
            const uint32_t nc = nt * 128u + wn * 64u + j * 8u + tt * 2u;
            float2 bv = *reinterpret_cast<const float2*>(bias + nc);
            float2 o0, o1;
            o0.x = fmaxf(fmaf((float)acc[i][j][0], sc, bv.x), 0.0f);
            o0.y = fmaxf(fmaf((float)acc[i][j][1], sc, bv.y), 0.0f);
            o1.x = fmaxf(fmaf((float)acc[i][j][2], sc, bv.x), 0.0f);
            o1.y = fmaxf(fmaf((float)acc[i][j][3], sc, bv.y), 0.0f);
            *reinterpret_cast<float2*>(orow0 + nc) = o0;
            *reinterpret_cast<float2*>(orow1 + nc) = o1;
        }
    }
}

// ======================= launch =======================
extern "C" void kernel_launch(void* const* d_in, const int* in_sizes, int n_in,
                              void* d_out, int out_size) {
    const float* x      = (const float*)d_in[0];  // hidden_states [2,2048,4096]
    const float* w      = (const float*)d_in[1];  // weight [16384,4096]
    const float* bias   = (const float*)d_in[2];  // bias [16384]
    const float* wclip  = (const float*)d_in[3];  // weight_clip_val
    const float* xclip  = (const float*)d_in[4];  // input_clip_val
    float* out = (float*)d_out;

    cudaFuncSetAttribute(gemm_kernel, cudaFuncAttributeMaxDynamicSharedMemorySize,
                         SMEM_SIZE);

    // total threads = M*K/16 = 1,048,576 -> 4096 blocks of 256
    quant_a_kernel<<<(M_DIM * (K_DIM / 16)) / 256, 256>>>(x, xclip);
    // total threads = N*K/8 = 8,388,608 -> 32768 blocks of 256
    quant_b_kernel<<<(N_DIM * (K_DIM / 8)) / 256, 256>>>(w, wclip);
    gemm_kernel<<<MT * NT, 128, SMEM_SIZE>>>(bias, wclip, xclip, out);
}

// round 5
// speedup vs baseline: 1.0157x; 1.0157x over previous
#include <cuda_runtime.h>
#include <cuda_bf16.h>
#include <cstdint>

// ======================= problem sizes =======================
constexpr int K_DIM = 4096;
constexpr int M_DIM = 4096;     // 2*2048 tokens
constexpr int N_DIM = 16384;

constexpr int BM = 128, BN = 128;
constexpr int MT = M_DIM / BM;   // 32
constexpr int NT = N_DIM / BN;   // 128
constexpr int KT2 = K_DIM / 128; // 32 k-chunks of 128
constexpr int STAGES = 3;

// scratch tile granularity (written by quant kernels, 64-k sub-tiles)
constexpr uint32_t A_TILE64 = 128 * 64;               // 8192 bytes
constexpr uint32_t B_TILE64 = 128 * 64;               // 8192 bytes
// GEMM stage = 2 consecutive 64-k sub-tiles per operand (contiguous in scratch)
constexpr uint32_t A_STG = 2 * A_TILE64;              // 16384
constexpr uint32_t B_STG = 2 * B_TILE64;              // 16384
constexpr uint32_t STAGE_B = A_STG + B_STG;           // 32768
constexpr uint32_t SMEM_STAGE0 = 1024;
constexpr uint32_t SMEM_SIZE = SMEM_STAGE0 + STAGES * STAGE_B;  // 99328

constexpr uint32_t OFF_FULL  = 0;    // full[s]  at 0 + 16*s
constexpr uint32_t OFF_EMPTY = 8;    // empty[s] at 8 + 16*s

// int8 quantized scratch in IMMA fragment order
__device__ __align__(1024) unsigned char g_Aq[(size_t)M_DIM * K_DIM]; // 16 MB
__device__ __align__(1024) unsigned char g_Bq[(size_t)N_DIM * K_DIM]; // 64 MB

// ======================= helpers =======================
static __device__ __forceinline__ uint32_t smem_u32(const void* p) {
    uint32_t a;
    asm("{ .reg .u64 t; cvta.to.shared.u64 t, %1; cvt.u32.u64 %0, t; }"
        : "=r"(a) : "l"(p));
    return a;
}
static __device__ __forceinline__ void mbar_init(uint32_t mbar, uint32_t cnt) {
    asm volatile("mbarrier.init.shared.b64 [%0], %1;" :: "r"(mbar), "r"(cnt) : "memory");
}
static __device__ __forceinline__ void mbar_expect_tx(uint32_t mbar, uint32_t bytes) {
    asm volatile("mbarrier.arrive.expect_tx.shared.b64 _, [%0], %1;"
                 :: "r"(mbar), "r"(bytes) : "memory");
}
static __device__ __forceinline__ void mbar_arrive(uint32_t mbar) {
    asm volatile("mbarrier.arrive.shared.b64 _, [%0];" :: "r"(mbar) : "memory");
}
static __device__ __forceinline__ void mbar_wait(uint32_t mbar, uint32_t parity) {
    asm volatile(
        "{\n\t.reg .pred P;\n\t"
        "W%=:\n\t"
        "mbarrier.try_wait.parity.acquire.cta.shared::cta.b64 P, [%0], %1, 0x989680;\n\t"
        "@P bra.uni D%=;\n\t"
        "bra.uni W%=;\n\t"
        "D%=:\n\t}"
        :: "r"(mbar), "r"(parity) : "memory");
}
static __device__ __forceinline__ void bulk_g2s(uint32_t dst, const void* src,
                                                uint32_t bytes, uint32_t mbar) {
    asm volatile(
        "cp.async.bulk.shared::cluster.global.mbarrier::complete_tx::bytes "
        "[%0], [%1], %2, [%3];"
        :: "r"(dst), "l"(src), "r"(bytes), "r"(mbar) : "memory");
}
static __device__ __forceinline__ void lds128(uint32_t& r0, uint32_t& r1,
                                              uint32_t& r2, uint32_t& r3, uint32_t a) {
    asm volatile("ld.shared.v4.b32 {%0,%1,%2,%3}, [%4];"
                 : "=r"(r0), "=r"(r1), "=r"(r2), "=r"(r3) : "r"(a));
}
static __device__ __forceinline__ void lds64(uint32_t& r0, uint32_t& r1, uint32_t a) {
    asm volatile("ld.shared.v2.b32 {%0,%1}, [%2];" : "=r"(r0), "=r"(r1) : "r"(a));
}
static __device__ __forceinline__ void imma16832(int& c0, int& c1, int& c2, int& c3,
                                                 uint32_t a0, uint32_t a1, uint32_t a2,
                                                 uint32_t a3, uint32_t b0, uint32_t b1) {
    asm volatile(
        "mma.sync.aligned.m16n8k32.row.col.s32.s8.s8.s32 "
        "{%0,%1,%2,%3}, {%4,%5,%6,%7}, {%8,%9}, {%0,%1,%2,%3};"
        : "+r"(c0), "+r"(c1), "+r"(c2), "+r"(c3)
        : "r"(a0), "r"(a1), "r"(a2), "r"(a3), "r"(b0), "r"(b1));
}
static __device__ __forceinline__ uint32_t quant_pack4(float4 v, float c, float inv) {
    int q0 = __float2int_rn(fminf(fmaxf(v.x, -c), c) * inv);
    int q1 = __float2int_rn(fminf(fmaxf(v.y, -c), c) * inv);
    int q2 = __float2int_rn(fminf(fmaxf(v.z, -c), c) * inv);
    int q3 = __float2int_rn(fminf(fmaxf(v.w, -c), c) * inv);
    return (uint32_t)(q0 & 255) | ((uint32_t)(q1 & 255) << 8) |
           ((uint32_t)(q2 & 255) << 16) | ((uint32_t)(q3 & 255) << 24);
}

// ======================= quantize kernels =======================
// A fragment order: 64k sub-tile(mt,kt) 8192B = [kc(2)][ma(8)] atoms of 512B,
// atom = [lane(32)][a0,a1,a2,a3]  (IMMA m16n8k32 A layout)
__global__ void __launch_bounds__(256) quant_a_kernel(const float* __restrict__ x,
                                                      const float* __restrict__ clip) {
    uint32_t t = blockIdx.x * 256u + threadIdx.x;
    uint32_t lane = t & 31u;
    uint32_t rest = t >> 5;
    uint32_t amkc = rest & 15u;           // kc*8 + ma
    uint32_t kt   = (rest >> 4) & 63u;
    uint32_t mt   = rest >> 10;
    uint32_t kc = amkc >> 3, ma = amkc & 7u;
    uint32_t g = lane >> 2, tt = lane & 3u;

    float c = fabsf(__ldg(clip));
    float inv = 127.0f / c;

    uint32_t row0 = mt * 128u + ma * 16u + g;
    uint32_t col0 = kt * 64u + kc * 32u + tt * 4u;
    const float* base = x + (size_t)row0 * K_DIM + col0;

    float4 f0 = *reinterpret_cast<const float4*>(base);
    float4 f1 = *reinterpret_cast<const float4*>(base + 8u * K_DIM);
    float4 f2 = *reinterpret_cast<const float4*>(base + 16);
    float4 f3 = *reinterpret_cast<const float4*>(base + 8u * K_DIM + 16);

    uint4 p;
    p.x = quant_pack4(f0, c, inv);
    p.y = quant_pack4(f1, c, inv);
    p.z = quant_pack4(f2, c, inv);
    p.w = quant_pack4(f3, c, inv);

    size_t off = ((size_t)(mt * 64u + kt) * 16u + amkc) * 512u + lane * 16u;
    *reinterpret_cast<uint4*>(g_Aq + off) = p;
}

// B fragment order: 64k sub-tile(nt,kt) 8192B = [kc(2)][na(16)] atoms of 256B,
// atom = [lane(32)][b0,b1]  (IMMA m16n8k32 B layout)
__global__ void __launch_bounds__(256) quant_b_kernel(const float* __restrict__ w,
                                                      const float* __restrict__ clip) {
    uint32_t t = blockIdx.x * 256u + threadIdx.x;
    uint32_t lane = t & 31u;
    uint32_t rest = t >> 5;
    uint32_t ankc = rest & 31u;           // kc*16 + na
    uint32_t kt   = (rest >> 5) & 63u;
    uint32_t nt   = rest >> 11;
    uint32_t kc = ankc >> 4, na = ankc & 15u;
    uint32_t g = lane >> 2, tt = lane & 3u;

    float c = fabsf(__ldg(clip));
    float inv = 127.0f / c;

    uint32_t n  = nt * 128u + na * 8u + g;
    uint32_t k0 = kt * 64u + kc * 32u + tt * 4u;
    const float* base = w + (size_t)n * K_DIM + k0;

    float4 f0 = *reinterpret_cast<const float4*>(base);
    float4 f1 = *reinterpret_cast<const float4*>(base + 16);

    uint2 p;
    p.x = quant_pack4(f0, c, inv);
    p.y = quant_pack4(f1, c, inv);

    size_t off = ((size_t)(nt * 64u + kt) * 32u + ankc) * 256u + lane * 8u;
    *reinterpret_cast<uint2*>(g_Bq + off) = p;
}

// ======================= GEMM kernel =======================
// 256 threads, warp grid 2(m) x 4(n), warp tile 64x32, BK=128 per stage.
__global__ void __launch_bounds__(256, 2) gemm_kernel(const float* __restrict__ bias,
                                                      const float* __restrict__ clip_w,
                                                      const float* __restrict__ clip_x,
                                                      float* __restrict__ out) {
    extern __shared__ unsigned char smem[];
    const uint32_t sb = smem_u32(smem);
    const int tid = threadIdx.x;
    const uint32_t lane = tid & 31, wid = tid >> 5;
    const uint32_t wm = wid & 1, wn = wid >> 1;   // wm in [0,2), wn in [0,4)
    const uint32_t g = lane >> 2, tt = lane & 3;

    const uint32_t bid = blockIdx.x;
    const uint32_t mt = bid & 31u;    // m-fastest: 32 CTAs share one B column
    const uint32_t nt = bid >> 5;

    if (tid == 0) {
        for (int s = 0; s < STAGES; s++) {
            mbar_init(sb + OFF_FULL  + 16u * s, 1);
            mbar_init(sb + OFF_EMPTY + 16u * s, 8);   // one arrive per warp
        }
    }
    __syncthreads();

    const unsigned char* aAg = g_Aq + (size_t)mt * (K_DIM / 64) * A_TILE64;
    const unsigned char* bAg = g_Bq + (size_t)nt * (K_DIM / 64) * B_TILE64;

    // prologue: fill all stages
    if (tid == 0) {
#pragma unroll
        for (int p = 0; p < STAGES; ++p) {
            uint32_t full = sb + OFF_FULL + 16u * p;
            uint32_t dst = sb + SMEM_STAGE0 + p * STAGE_B;
            mbar_expect_tx(full, STAGE_B);
            bulk_g2s(dst,         aAg + (size_t)p * A_STG, A_STG, full);
            bulk_g2s(dst + A_STG, bAg + (size_t)p * B_STG, B_STG, full);
        }
    }

    int acc[4][4][4];
#pragma unroll
    for (int i = 0; i < 4; i++)
#pragma unroll
        for (int j = 0; j < 4; j++)
#pragma unroll
            for (int r = 0; r < 4; r++) acc[i][j][r] = 0;

    // A: wm selects 4 of 8 ma atoms; per-kcc stride 4096 (contiguous sub-tiles)
    const uint32_t aLane = lane * 16u + wm * (4u * 512u);
    // B: wn selects 4 of 16 na atoms
    const uint32_t bLane = lane * 8u + wn * (4u * 256u);

    int s = 0; uint32_t ph = 0;
    for (int kt2 = 0; kt2 < KT2; ++kt2) {
        const uint32_t stage = sb + SMEM_STAGE0 + s * STAGE_B;

        mbar_wait(sb + OFF_FULL + 16u * s, ph);

#pragma unroll
        for (int kcc = 0; kcc < 4; ++kcc) {   // 4 chunks of k32
            uint32_t a[4][4], b[4][2];
            const uint32_t aBase = stage + kcc * 4096u + aLane;
            const uint32_t bBase = stage + A_STG + kcc * 4096u + bLane;
#pragma unroll
            for (int i = 0; i < 4; ++i)
                lds128(a[i][0], a[i][1], a[i][2], a[i][3], aBase + i * 512u);
#pragma unroll
            for (int j = 0; j < 4; ++j)
                lds64(b[j][0], b[j][1], bBase + j * 256u);
#pragma unroll
            for (int i = 0; i < 4; ++i)
#pragma unroll
                for (int j = 0; j < 4; ++j)
                    imma16832(acc[i][j][0], acc[i][j][1], acc[i][j][2], acc[i][j][3],
                              a[i][0], a[i][1], a[i][2], a[i][3], b[j][0], b[j][1]);
        }

        if (lane == 0) mbar_arrive(sb + OFF_EMPTY + 16u * s);

        if (tid == 0) {
            int nk = kt2 + STAGES;
            if (nk < KT2) {
                mbar_wait(sb + OFF_EMPTY + 16u * s, ph);
                uint32_t full = sb + OFF_FULL + 16u * s;
                mbar_expect_tx(full, STAGE_B);
                bulk_g2s(stage,         aAg + (size_t)nk * A_STG, A_STG, full);
                bulk_g2s(stage + A_STG, bAg + (size_t)nk * B_STG, B_STG, full);
            }
        }

        if (++s == STAGES) { s = 0; ph ^= 1; }
    }

    // -------- epilogue --------
    const float sc = (fabsf(__ldg(clip_x)) / 127.0f) * (fabsf(__ldg(clip_w)) / 127.0f);

#pragma unroll
    for (int i = 0; i < 4; ++i) {
        const uint32_t r0 = mt * 128u + wm * 64u + i * 16u + g;
        float* orow0 = out + (size_t)r0 * N_DIM;
        float* orow1 = orow0 + (size_t)8 * N_DIM;
#pragma unroll
        for (int j = 0; j < 4; ++j) {
            const uint32_t nc = nt * 128u + wn * 32u + j * 8u + tt * 2u;
            float2 bv = *reinterpret_cast<const float2*>(bias + nc);
            float2 o0, o1;
            o0.x = fmaxf(fmaf((float)acc[i][j][0], sc, bv.x), 0.0f);
            o0.y = fmaxf(fmaf((float)acc[i][j][1], sc, bv.y), 0.0f);
            o1.x = fmaxf(fmaf((float)acc[i][j][2], sc, bv.x), 0.0f);
            o1.y = fmaxf(fmaf((float)acc[i][j][3], sc, bv.y), 0.0f);
            *reinterpret_cast<float2*>(orow0 + nc) = o0;
            *reinterpret_cast<float2*>(orow1 + nc) = o1;
        }
    }
}

// ======================= launch =======================
extern "C" void kernel_launch(void* const* d_in, const int* in_sizes, int n_in,
                              void* d_out, int out_size) {
    const float* x      = (const float*)d_in[0];  // hidden_states [2,2048,4096]
    const float* w      = (const float*)d_in[1];  // weight [16384,4096]
    const float* bias   = (const float*)d_in[2];  // bias [16384]
    const float* wclip  = (const float*)d_in[3];  // weight_clip_val
    const float* xclip  = (const float*)d_in[4];  // input_clip_val
    float* out = (float*)d_out;

    cudaFuncSetAttribute(gemm_kernel, cudaFuncAttributeMaxDynamicSharedMemorySize,
                         SMEM_SIZE);

    // total threads = M*K/16 = 1,048,576 -> 4096 blocks of 256
    quant_a_kernel<<<(M_DIM * (K_DIM / 16)) / 256, 256>>>(x, xclip);
    // total threads = N*K/8 = 8,388,608 -> 32768 blocks of 256
    quant_b_kernel<<<(N_DIM * (K_DIM / 8)) / 256, 256>>>(w, wclip);
    gemm_kernel<<<MT * NT, 256, SMEM_SIZE>>>(bias, wclip, xclip, out);
}

// round 6
// speedup vs baseline: 7.1386x; 7.0284x over previous
#include <cuda_runtime.h>
#include <cuda_bf16.h>
#include <cstdint>

// Feature gate: true only when compiling an arch-specific ('a') device pass.
#if defined(__CUDA_ARCH_FEAT_SM103_ALL) || defined(__CUDA_ARCH_FEAT_SM100_ALL)
#define HAS_TC 1
#else
#define HAS_TC 0
#endif

// ======================= problem sizes =======================
constexpr int K_DIM = 4096;
constexpr int M_DIM = 4096;     // 2*2048 tokens
constexpr int N_DIM = 16384;

// ---- tcgen05 path tiling: BM=128, BN=256, BK=64, 64 k-tiles, 4 stages ----
constexpr int TC_KT = 64;
constexpr int TC_STAGES = 4;
constexpr uint32_t TC_AT = 128 * 64 * 2;          // 16384 B (bf16)
constexpr uint32_t TC_BT = 256 * 64 * 2;          // 32768 B
constexpr uint32_t TC_STG = TC_AT + TC_BT;        // 49152
constexpr uint32_t SMEM_DATA0 = 1024;
constexpr uint32_t SMEM_SIZE = SMEM_DATA0 + TC_STAGES * TC_STG;  // 197632

// ---- fallback path tiling: BM=128, BN=128 (2 halves), BK=64, 4 stages ----
constexpr int F_STAGES = 4;
constexpr uint32_t F_AT = 8192, F_BT = 8192, F_STG = 16384;

// barrier smem offsets (shared by both paths; data starts at 1024)
constexpr uint32_t OFF_TMEM  = 0;
constexpr uint32_t OFF_FULL  = 16;   // full[s]  at 16 + 16*s
constexpr uint32_t OFF_EMPTY = 24;   // empty[s] at 24 + 16*s
constexpr uint32_t OFF_DONE  = 96;

// idesc: kind::f16, dtype=F32(1<<4), atype=BF16(1<<7), btype=BF16(1<<10),
// N=256 -> 32<<17, M=128 -> 8<<24
constexpr uint32_t MMA_IDESC = 0x08400490u;
// SW128 K-major smem descriptor base (layout=SW128, version=1, SBO=64, LBO=1)
constexpr uint64_t DESC_BASE = 0x4000404000010000ULL;

// quantized scratch
__device__ __align__(1024) unsigned char g_A8 [(size_t)M_DIM * K_DIM];      // 16 MB int8 frag
__device__ __align__(1024) unsigned char g_B8 [(size_t)N_DIM * K_DIM];      // 64 MB int8 frag
__device__ __align__(1024) unsigned char g_Abf[(size_t)M_DIM * K_DIM * 2];  // 32 MB bf16 SW128
__device__ __align__(1024) unsigned char g_Bbf[(size_t)N_DIM * K_DIM * 2];  // 128 MB bf16 SW128

// ======================= common helpers =======================
static __device__ __forceinline__ uint32_t smem_u32(const void* p) {
    uint32_t a;
    asm("{ .reg .u64 t; cvta.to.shared.u64 t, %1; cvt.u32.u64 %0, t; }"
        : "=r"(a) : "l"(p));
    return a;
}
static __device__ __forceinline__ uint32_t swz128(uint32_t off) {
    return off ^ ((off >> 3) & 0x70u);
}
static __device__ __forceinline__ void mbar_init(uint32_t mbar, uint32_t cnt) {
    asm volatile("mbarrier.init.shared.b64 [%0], %1;" :: "r"(mbar), "r"(cnt) : "memory");
}
static __device__ __forceinline__ void mbar_expect_tx(uint32_t mbar, uint32_t bytes) {
    asm volatile("mbarrier.arrive.expect_tx.shared.b64 _, [%0], %1;"
                 :: "r"(mbar), "r"(bytes) : "memory");
}
static __device__ __forceinline__ void mbar_arrive(uint32_t mbar) {
    asm volatile("mbarrier.arrive.shared.b64 _, [%0];" :: "r"(mbar) : "memory");
}
static __device__ __forceinline__ void mbar_wait(uint32_t mbar, uint32_t parity) {
    asm volatile(
        "{\n\t.reg .pred P;\n\t"
        "W%=:\n\t"
        "mbarrier.try_wait.parity.acquire.cta.shared::cta.b64 P, [%0], %1, 0x989680;\n\t"
        "@P bra.uni D%=;\n\t"
        "bra.uni W%=;\n\t"
        "D%=:\n\t}"
        :: "r"(mbar), "r"(parity) : "memory");
}
static __device__ __forceinline__ void bulk_g2s(uint32_t dst, const void* src,
                                                uint32_t bytes, uint32_t mbar) {
    asm volatile(
        "cp.async.bulk.shared::cluster.global.mbarrier::complete_tx::bytes "
        "[%0], [%1], %2, [%3];"
        :: "r"(dst), "l"(src), "r"(bytes), "r"(mbar) : "memory");
}
static __device__ __forceinline__ uint32_t quant_pack4(float4 v, float c, float inv) {
    int q0 = __float2int_rn(fminf(fmaxf(v.x, -c), c) * inv);
    int q1 = __float2int_rn(fminf(fmaxf(v.y, -c), c) * inv);
    int q2 = __float2int_rn(fminf(fmaxf(v.z, -c), c) * inv);
    int q3 = __float2int_rn(fminf(fmaxf(v.w, -c), c) * inv);
    return (uint32_t)(q0 & 255) | ((uint32_t)(q1 & 255) << 8) |
           ((uint32_t)(q2 & 255) << 16) | ((uint32_t)(q3 & 255) << 24);
}

#if !HAS_TC
// legacy fallback helpers
static __device__ __forceinline__ void lds128(uint32_t& r0, uint32_t& r1,
                                              uint32_t& r2, uint32_t& r3, uint32_t a) {
    asm volatile("ld.shared.v4.b32 {%0,%1,%2,%3}, [%4];"
                 : "=r"(r0), "=r"(r1), "=r"(r2), "=r"(r3) : "r"(a));
}
static __device__ __forceinline__ void lds64(uint32_t& r0, uint32_t& r1, uint32_t a) {
    asm volatile("ld.shared.v2.b32 {%0,%1}, [%2];" : "=r"(r0), "=r"(r1) : "r"(a));
}
static __device__ __forceinline__ void imma16832(int& c0, int& c1, int& c2, int& c3,
                                                 uint32_t a0, uint32_t a1, uint32_t a2,
                                                 uint32_t a3, uint32_t b0, uint32_t b1) {
    asm volatile(
        "mma.sync.aligned.m16n8k32.row.col.s32.s8.s8.s32 "
        "{%0,%1,%2,%3}, {%4,%5,%6,%7}, {%8,%9}, {%0,%1,%2,%3};"
        : "+r"(c0), "+r"(c1), "+r"(c2), "+r"(c3)
        : "r"(a0), "r"(a1), "r"(a2), "r"(a3), "r"(b0), "r"(b1));
}
#endif

#if HAS_TC
// tcgen05 helpers ('a' pass only)
static __device__ __forceinline__ void tc_commit(uint32_t mbar) {
    asm volatile(
        "tcgen05.commit.cta_group::1.mbarrier::arrive::one.shared::cluster.b64 [%0];"
        :: "r"(mbar) : "memory");
}
static __device__ __forceinline__ void mma_bf16_ss(uint32_t d_tmem, uint64_t ad,
                                                   uint64_t bd, uint32_t enable_d) {
    asm volatile(
        "{\n\t.reg .pred p;\n\t"
        "setp.ne.u32 p, %5, 0;\n\t"
        "tcgen05.mma.cta_group::1.kind::f16 [%0], %1, %2, %3, {%4, %4, %4, %4}, p;\n\t"
        "}"
        :: "r"(d_tmem), "l"(ad), "l"(bd), "r"(MMA_IDESC), "r"(0u), "r"(enable_d)
        : "memory");
}
#define TC_ALLOC(smaddr, n) \
    asm volatile("tcgen05.alloc.cta_group::1.sync.aligned.shared::cta.b32 [%0], %1;" \
                 :: "r"(smaddr), "r"(n) : "memory")
#define TC_RELINQ() \
    asm volatile("tcgen05.relinquish_alloc_permit.cta_group::1.sync.aligned;")
#define TC_DEALLOC(tmem, n) \
    asm volatile("tcgen05.dealloc.cta_group::1.sync.aligned.b32 %0, %1;" :: "r"(tmem), "r"(n))
#define TC_FENCE_AFTER()  asm volatile("tcgen05.fence::after_thread_sync;" ::: "memory")
#define TC_WAIT_LD()      asm volatile("tcgen05.wait::ld.sync.aligned;" ::: "memory")
#define TC_LD_X32(r, tmem_addr) \
    asm volatile( \
        "tcgen05.ld.sync.aligned.32x32b.x32.b32 " \
        "{%0, %1, %2, %3, %4, %5, %6, %7, " \
        " %8, %9, %10, %11, %12, %13, %14, %15, " \
        " %16, %17, %18, %19, %20, %21, %22, %23, " \
        " %24, %25, %26, %27, %28, %29, %30, %31}, [%32];" \
        : "=r"((r)[0]),  "=r"((r)[1]),  "=r"((r)[2]),  "=r"((r)[3]), \
          "=r"((r)[4]),  "=r"((r)[5]),  "=r"((r)[6]),  "=r"((r)[7]), \
          "=r"((r)[8]),  "=r"((r)[9]),  "=r"((r)[10]), "=r"((r)[11]), \
          "=r"((r)[12]), "=r"((r)[13]), "=r"((r)[14]), "=r"((r)[15]), \
          "=r"((r)[16]), "=r"((r)[17]), "=r"((r)[18]), "=r"((r)[19]), \
          "=r"((r)[20]), "=r"((r)[21]), "=r"((r)[22]), "=r"((r)[23]), \
          "=r"((r)[24]), "=r"((r)[25]), "=r"((r)[26]), "=r"((r)[27]), \
          "=r"((r)[28]), "=r"((r)[29]), "=r"((r)[30]), "=r"((r)[31]) \
        : "r"(tmem_addr))
#endif

// ======================= quantize kernels: int8 IMMA-fragment (fallback) =======================
// Same proven layouts as R4/R5. Early-return when the tcgen05 path is active.
__global__ void __launch_bounds__(256) quant_a8(const float* __restrict__ x,
                                                const float* __restrict__ clip) {
#if HAS_TC
    return;
#else
    uint32_t t = blockIdx.x * 256u + threadIdx.x;     // M*K/16 threads
    uint32_t lane = t & 31u;
    uint32_t rest = t >> 5;
    uint32_t amkc = rest & 15u;
    uint32_t kt   = (rest >> 4) & 63u;
    uint32_t mt   = rest >> 10;
    uint32_t kc = amkc >> 3, ma = amkc & 7u;
    uint32_t g = lane >> 2, tt = lane & 3u;

    float c = fabsf(__ldg(clip));
    float inv = 127.0f / c;

    uint32_t row0 = mt * 128u + ma * 16u + g;
    uint32_t col0 = kt * 64u + kc * 32u + tt * 4u;
    const float* base = x + (size_t)row0 * K_DIM + col0;

    float4 f0 = *reinterpret_cast<const float4*>(base);
    float4 f1 = *reinterpret_cast<const float4*>(base + 8u * K_DIM);
    float4 f2 = *reinterpret_cast<const float4*>(base + 16);
    float4 f3 = *reinterpret_cast<const float4*>(base + 8u * K_DIM + 16);

    uint4 p;
    p.x = quant_pack4(f0, c, inv);
    p.y = quant_pack4(f1, c, inv);
    p.z = quant_pack4(f2, c, inv);
    p.w = quant_pack4(f3, c, inv);

    size_t off = ((size_t)(mt * 64u + kt) * 16u + amkc) * 512u + lane * 16u;
    *reinterpret_cast<uint4*>(g_A8 + off) = p;
#endif
}

__global__ void __launch_bounds__(256) quant_b8(const float* __restrict__ w,
                                                const float* __restrict__ clip) {
#if HAS_TC
    return;
#else
    uint32_t t = blockIdx.x * 256u + threadIdx.x;     // N*K/8 threads
    uint32_t lane = t & 31u;
    uint32_t rest = t >> 5;
    uint32_t ankc = rest & 31u;
    uint32_t kt   = (rest >> 5) & 63u;
    uint32_t nt   = rest >> 11;
    uint32_t kc = ankc >> 4, na = ankc & 15u;
    uint32_t g = lane >> 2, tt = lane & 3u;

    float c = fabsf(__ldg(clip));
    float inv = 127.0f / c;

    uint32_t n  = nt * 128u + na * 8u + g;
    uint32_t k0 = kt * 64u + kc * 32u + tt * 4u;
    const float* base = w + (size_t)n * K_DIM + k0;

    float4 f0 = *reinterpret_cast<const float4*>(base);
    float4 f1 = *reinterpret_cast<const float4*>(base + 16);

    uint2 p;
    p.x = quant_pack4(f0, c, inv);
    p.y = quant_pack4(f1, c, inv);

    size_t off = ((size_t)(nt * 64u + kt) * 32u + ankc) * 256u + lane * 8u;
    *reinterpret_cast<uint2*>(g_B8 + off) = p;
#endif
}

// ======================= quantize kernels: bf16 SW128 tiles (tcgen05) =======================
// A tiles: [mt(32)][kt(64)] of 128 rows x 128B (64 bf16), SW128-swizzled.
// B tiles: [nt(64)][kt(64)] of 256 rows x 128B, SW128-swizzled.
__global__ void __launch_bounds__(256) quant_abf(const float* __restrict__ x,
                                                 const float* __restrict__ clip) {
#if !HAS_TC
    return;
#else
    uint32_t t = blockIdx.x * 256u + threadIdx.x;     // M*K/8 threads
    float c = fabsf(__ldg(clip));
    float inv = 127.0f / c;
    uint32_t k0 = (t & 511u) << 3;
    uint32_t m  = t >> 9;
    const float4* s = reinterpret_cast<const float4*>(x + (size_t)m * K_DIM + k0);
    float4 a = s[0], b = s[1];
    float v[8] = {a.x, a.y, a.z, a.w, b.x, b.y, b.z, b.w};
    union { uint4 u; __nv_bfloat16 h[8]; } p;
#pragma unroll
    for (int i = 0; i < 8; i++) {
        float xc = fminf(fmaxf(v[i], -c), c);
        p.h[i] = __float2bfloat16_rn(rintf(xc * inv));
    }
    uint32_t mt = m >> 7, r = m & 127u, kt = k0 >> 6, cc = k0 & 63u;
    size_t tile = ((size_t)(mt * 64u + kt)) * (size_t)TC_AT;
    uint32_t off = swz128(r * 128u + cc * 2u);
    *reinterpret_cast<uint4*>(g_Abf + tile + off) = p.u;
#endif
}

__global__ void __launch_bounds__(256) quant_bbf(const float* __restrict__ w,
                                                 const float* __restrict__ clip) {
#if !HAS_TC
    return;
#else
    uint32_t t = blockIdx.x * 256u + threadIdx.x;     // N*K/8 threads
    float c = fabsf(__ldg(clip));
    float inv = 127.0f / c;
    uint32_t k0 = (t & 511u) << 3;
    uint32_t n  = t >> 9;
    const float4* s = reinterpret_cast<const float4*>(w + (size_t)n * K_DIM + k0);
    float4 a = s[0], b = s[1];
    float v[8] = {a.x, a.y, a.z, a.w, b.x, b.y, b.z, b.w};
    union { uint4 u; __nv_bfloat16 h[8]; } p;
#pragma unroll
    for (int i = 0; i < 8; i++) {
        float xc = fminf(fmaxf(v[i], -c), c);
        p.h[i] = __float2bfloat16_rn(rintf(xc * inv));
    }
    uint32_t nt = n >> 8, r = n & 255u, kt = k0 >> 6, cc = k0 & 63u;
    size_t tile = ((size_t)(nt * 64u + kt)) * (size_t)TC_BT;
    uint32_t off = swz128(r * 128u + cc * 2u);
    *reinterpret_cast<uint4*>(g_Bbf + tile + off) = p.u;
#endif
}

// ======================= unified GEMM kernel =======================
// grid = 2048 (mt 0..31 fastest, nt 0..63), 128 threads, dyn smem 197632.
// out[m][n] = relu( sc * sum_k qx[m][k]*qw[n][k] + bias[n] )
__global__ void __launch_bounds__(128, 1) gemm_kernel(const float* __restrict__ bias,
                                                      const float* __restrict__ clip_w,
                                                      const float* __restrict__ clip_x,
                                                      float* __restrict__ out) {
    extern __shared__ unsigned char smem[];
    const uint32_t sb = smem_u32(smem);
    const int tid = threadIdx.x;
    const uint32_t bid = blockIdx.x;
    const uint32_t mt = bid & 31u;
    const uint32_t nt = bid >> 5;          // 0..63 (BN=256 column)
    const float sc = (fabsf(__ldg(clip_x)) / 127.0f) * (fabsf(__ldg(clip_w)) / 127.0f);

#if HAS_TC
    // ---------------- tcgen05 path ----------------
    if (tid < 32) TC_ALLOC(sb + OFF_TMEM, 256);
    if (tid == 0) {
        for (int s = 0; s < TC_STAGES; s++) {
            mbar_init(sb + OFF_FULL  + 16u * s, 1);
            mbar_init(sb + OFF_EMPTY + 16u * s, 1);
        }
        mbar_init(sb + OFF_DONE, 1);
    }
    __syncthreads();
    uint32_t tmem;
    asm volatile("ld.shared.b32 %0, [%1];" : "=r"(tmem) : "r"(sb + OFF_TMEM));
    if (tid < 32) TC_RELINQ();

    if (tid == 0) {
        const unsigned char* asrc = g_Abf + (size_t)mt * TC_KT * TC_AT;
        const unsigned char* bsrc = g_Bbf + (size_t)nt * TC_KT * TC_BT;
        int s = 0; uint32_t ph = 1;
        for (int kt = 0; kt < TC_KT; ++kt) {
            mbar_wait(sb + OFF_EMPTY + 16u * s, ph);
            uint32_t full = sb + OFF_FULL + 16u * s;
            mbar_expect_tx(full, TC_STG);
            uint32_t dst = sb + SMEM_DATA0 + s * TC_STG;
            bulk_g2s(dst,         asrc + (size_t)kt * TC_AT, TC_AT, full);
            bulk_g2s(dst + TC_AT, bsrc + (size_t)kt * TC_BT, TC_BT, full);
            if (++s == TC_STAGES) { s = 0; ph ^= 1; }
        }
    } else if (tid == 32) {
        int s = 0; uint32_t ph = 0, en = 0;
        for (int kt = 0; kt < TC_KT; ++kt) {
            mbar_wait(sb + OFF_FULL + 16u * s, ph);
            uint32_t base = sb + SMEM_DATA0 + s * TC_STG;
            uint64_t ad = DESC_BASE | ((uint64_t)(base >> 4) & 0x3FFFu);
            uint64_t bd = DESC_BASE | ((uint64_t)((base + TC_AT) >> 4) & 0x3FFFu);
#pragma unroll
            for (int ks = 0; ks < 4; ++ks) {   // 4 x K16 per BK=64 stage
                mma_bf16_ss(tmem, ad + ks * 2, bd + ks * 2, en);
                en = 1;
            }
            tc_commit(sb + OFF_EMPTY + 16u * s);
            if (++s == TC_STAGES) { s = 0; ph ^= 1; }
        }
        tc_commit(sb + OFF_DONE);
    }

    mbar_wait(sb + OFF_DONE, 0);
    TC_FENCE_AFTER();

    {
        const int wid = tid >> 5, lid = tid & 31;
        const uint32_t m = mt * 128u + wid * 32 + lid;
        float* orow = out + (size_t)m * N_DIM + (size_t)nt * 256u;
        const float* bp = bias + (size_t)nt * 256u;
#pragma unroll 1
        for (int cb = 0; cb < 256; cb += 32) {
            uint32_t r[32];
            TC_LD_X32(r, tmem + cb);
            TC_WAIT_LD();
#pragma unroll
            for (int j = 0; j < 32; j += 4) {
                float4 bv = *reinterpret_cast<const float4*>(bp + cb + j);
                float4 o;
                o.x = fmaxf(fmaf(__uint_as_float(r[j + 0]), sc, bv.x), 0.0f);
                o.y = fmaxf(fmaf(__uint_as_float(r[j + 1]), sc, bv.y), 0.0f);
                o.z = fmaxf(fmaf(__uint_as_float(r[j + 2]), sc, bv.z), 0.0f);
                o.w = fmaxf(fmaf(__uint_as_float(r[j + 3]), sc, bv.w), 0.0f);
                *reinterpret_cast<float4*>(orow + cb + j) = o;
            }
        }
    }

    __syncthreads();
    if (tid < 32) TC_DEALLOC(tmem, 256);

#else
    // ---------------- legacy IMMA fallback ----------------
    // Flattened 128-iteration pipeline: iterations 0..63 = n-half 0 (BN=128),
    // 64..127 = n-half 1. A tiles repeat; B switches column block at it=64.
    const uint32_t lane = tid & 31, wid = tid >> 5;
    const uint32_t wm = wid & 1, wn = wid >> 1;   // 2x2 warp grid, warp tile 64x64
    const uint32_t g = lane >> 2, tt = lane & 3;

    if (tid == 0) {
        for (int s = 0; s < F_STAGES; s++) {
            mbar_init(sb + OFF_FULL  + 16u * s, 1);
            mbar_init(sb + OFF_EMPTY + 16u * s, 128);
        }
    }
    __syncthreads();

    const unsigned char* aAg = g_A8 + (size_t)mt * 64u * F_AT;
    const unsigned char* bAg = g_B8 + (size_t)(nt * 2u) * 64u * F_BT;  // two halves contiguous

    if (tid == 0) {
#pragma unroll
        for (int p = 0; p < F_STAGES; ++p) {
            uint32_t full = sb + OFF_FULL + 16u * p;
            uint32_t dst = sb + SMEM_DATA0 + p * F_STG;
            mbar_expect_tx(full, F_STG);
            bulk_g2s(dst,        aAg + (size_t)p * F_AT, F_AT, full);
            bulk_g2s(dst + F_AT, bAg + (size_t)p * F_BT, F_BT, full);
        }
    }

    int acc[4][8][4];
#pragma unroll
    for (int i = 0; i < 4; i++)
#pragma unroll
        for (int j = 0; j < 8; j++)
#pragma unroll
            for (int r = 0; r < 4; r++) acc[i][j][r] = 0;

    const uint32_t aLane = lane * 16u + wm * (4u * 512u);
    const uint32_t bLane = lane * 8u + wn * (8u * 256u);

    for (int it = 0; it < 128; ++it) {
        const int s = it & 3;
        const uint32_t ph = (it >> 2) & 1u;
        const uint32_t stage = sb + SMEM_DATA0 + s * F_STG;

        mbar_wait(sb + OFF_FULL + 16u * s, ph);

#pragma unroll
        for (int kc = 0; kc < 2; ++kc) {
            uint32_t a[4][4], b[8][2];
            const uint32_t aBase = stage + kc * 4096u + aLane;
            const uint32_t bBase = stage + F_AT + kc * 4096u + bLane;
#pragma unroll
            for (int i = 0; i < 4; ++i)
                lds128(a[i][0], a[i][1], a[i][2], a[i][3], aBase + i * 512u);
#pragma unroll
            for (int j = 0; j < 8; ++j)
                lds64(b[j][0], b[j][1], bBase + j * 256u);
#pragma unroll
            for (int i = 0; i < 4; ++i)
#pragma unroll
                for (int j = 0; j < 8; ++j)
                    imma16832(acc[i][j][0], acc[i][j][1], acc[i][j][2], acc[i][j][3],
                              a[i][0], a[i][1], a[i][2], a[i][3], b[j][0], b[j][1]);
        }

        mbar_arrive(sb + OFF_EMPTY + 16u * s);

        if ((it & 63) == 63) {
            // epilogue for this n-half, then reset accumulators
            const uint32_t half = (uint32_t)(it >> 6);
#pragma unroll
            for (int i = 0; i < 4; ++i) {
                const uint32_t r0 = mt * 128u + wm * 64u + i * 16u + g;
                float* orow0 = out + (size_t)r0 * N_DIM;
                float* orow1 = orow0 + (size_t)8 * N_DIM;
#pragma unroll
                for (int j = 0; j < 8; ++j) {
                    const uint32_t nc = nt * 256u + half * 128u + wn * 64u + j * 8u + tt * 2u;
                    float2 bv = *reinterpret_cast<const float2*>(bias + nc);
                    float2 o0, o1;
                    o0.x = fmaxf(fmaf((float)acc[i][j][0], sc, bv.x), 0.0f);
                    o0.y = fmaxf(fmaf((float)acc[i][j][1], sc, bv.y), 0.0f);
                    o1.x = fmaxf(fmaf((float)acc[i][j][2], sc, bv.x), 0.0f);
                    o1.y = fmaxf(fmaf((float)acc[i][j][3], sc, bv.y), 0.0f);
                    *reinterpret_cast<float2*>(orow0 + nc) = o0;
                    *reinterpret_cast<float2*>(orow1 + nc) = o1;
                    acc[i][j][0] = acc[i][j][1] = acc[i][j][2] = acc[i][j][3] = 0;
                }
            }
        }

        if (tid == 0) {
            int nk = it + F_STAGES;
            if (nk < 128) {
                mbar_wait(sb + OFF_EMPTY + 16u * s, ph);
                uint32_t full = sb + OFF_FULL + 16u * s;
                mbar_expect_tx(full, F_STG);
                // A repeats every 64; B runs linearly through both halves (contiguous)
                bulk_g2s(stage,        aAg + (size_t)(nk & 63) * F_AT, F_AT, full);
                bulk_g2s(stage + F_AT, bAg + (size_t)nk * F_BT, F_BT, full);
            }
        }
    }
#endif
}

// ======================= launch =======================
extern "C" void kernel_launch(void* const* d_in, const int* in_sizes, int n_in,
                              void* d_out, int out_size) {
    const float* x      = (const float*)d_in[0];  // hidden_states [2,2048,4096]
    const float* w      = (const float*)d_in[1];  // weight [16384,4096]
    const float* bias   = (const float*)d_in[2];  // bias [16384]
    const float* wclip  = (const float*)d_in[3];  // weight_clip_val
    const float* xclip  = (const float*)d_in[4];  // input_clip_val
    float* out = (float*)d_out;

    cudaFuncSetAttribute(gemm_kernel, cudaFuncAttributeMaxDynamicSharedMemorySize,
                         SMEM_SIZE);

    // int8 fragment scratch (fallback path; early-returns under tcgen05)
    quant_a8<<<(M_DIM * (K_DIM / 16)) / 256, 256>>>(x, xclip);   // 4096 blocks
    quant_b8<<<(N_DIM * (K_DIM / 8)) / 256, 256>>>(w, wclip);    // 32768 blocks
    // bf16 SW128 scratch (tcgen05 path; early-returns otherwise)
    quant_abf<<<(M_DIM * (K_DIM / 8)) / 256, 256>>>(x, xclip);   // 8192 blocks
    quant_bbf<<<(N_DIM * (K_DIM / 8)) / 256, 256>>>(w, wclip);   // 32768 blocks

    gemm_kernel<<<32 * 64, 128, SMEM_SIZE>>>(bias, wclip, xclip, out);
}